// round 1
// baseline (speedup 1.0000x reference)
#include <cuda_runtime.h>

// out = feat @ Wv + bv
//
// The reference's softmax over axis=-2 (j) followed by einsum('ijk,ik->ik')
// (a sum over j) makes the attention-weight branch sum to exactly 1 per
// (i,k), so out[i,k] == v[i,k] == (feat @ Wv + bv)[i,k].
//
// feat: [N=1024, C=256] f32   (d_in[0])
// Wv:   [C, C]          f32   (d_in[9])
// bv:   [C]             f32   (d_in[10])
// out:  [N, C]          f32

namespace {

constexpr int Ndim = 1024;
constexpr int Cdim = 256;
constexpr int TM = 32;   // rows per block
constexpr int TN = 64;   // cols per block
constexpr int KC = 64;   // k-chunk

__global__ __launch_bounds__(256, 2)
void vgemm_bias_kernel(const float* __restrict__ A,   // [N, C] feat
                       const float* __restrict__ B,   // [C, C] Wv
                       const float* __restrict__ bias,// [C]
                       float* __restrict__ O)         // [N, C]
{
    __shared__ float sA[TM][KC];   // A tile, row-major (direct copy)
    __shared__ float sB[KC][TN];   // B tile, row-major (direct copy)

    const int tid = threadIdx.x;       // 0..255
    const int tx  = tid & 15;          // col group: 16 groups of 4 cols
    const int ty  = tid >> 4;          // row group: 16 groups of 2 rows

    const int row0 = blockIdx.y * TM;  // 0..992
    const int col0 = blockIdx.x * TN;  // 0..192

    float acc[2][4] = {{0.f,0.f,0.f,0.f},{0.f,0.f,0.f,0.f}};

    for (int kk = 0; kk < Cdim; kk += KC) {
        // --- load A tile: 32 rows x 64 k = 2048 floats; 8 floats/thread ---
        {
            const int m = tid >> 3;            // 0..31
            const int k = (tid & 7) * 8;       // 0,8,...,56
            const float* gp = &A[(row0 + m) * Cdim + kk + k];
            float4 v0 = *reinterpret_cast<const float4*>(gp);
            float4 v1 = *reinterpret_cast<const float4*>(gp + 4);
            *reinterpret_cast<float4*>(&sA[m][k])     = v0;
            *reinterpret_cast<float4*>(&sA[m][k + 4]) = v1;
        }
        // --- load B tile: 64 k x 64 n = 4096 floats; 16 floats/thread ---
        {
            #pragma unroll
            for (int r = 0; r < 4; r++) {
                const int idx = tid + r * 256;     // 0..1023 (float4 index)
                const int k   = idx >> 4;          // 0..63
                const int n   = (idx & 15) * 4;    // 0..60
                float4 v = *reinterpret_cast<const float4*>(
                    &B[(kk + k) * Cdim + col0 + n]);
                *reinterpret_cast<float4*>(&sB[k][n]) = v;
            }
        }
        __syncthreads();

        // --- 2x4 register micro-tile over the k-chunk ---
        #pragma unroll
        for (int k = 0; k < KC; k++) {
            const float a0 = sA[ty * 2 + 0][k];
            const float a1 = sA[ty * 2 + 1][k];
            const float4 b = *reinterpret_cast<const float4*>(&sB[k][tx * 4]);
            acc[0][0] = fmaf(a0, b.x, acc[0][0]);
            acc[0][1] = fmaf(a0, b.y, acc[0][1]);
            acc[0][2] = fmaf(a0, b.z, acc[0][2]);
            acc[0][3] = fmaf(a0, b.w, acc[0][3]);
            acc[1][0] = fmaf(a1, b.x, acc[1][0]);
            acc[1][1] = fmaf(a1, b.y, acc[1][1]);
            acc[1][2] = fmaf(a1, b.z, acc[1][2]);
            acc[1][3] = fmaf(a1, b.w, acc[1][3]);
        }
        __syncthreads();
    }

    // --- epilogue: add bias, write out ---
    const int col = col0 + tx * 4;
    const float4 bv4 = *reinterpret_cast<const float4*>(&bias[col]);
    #pragma unroll
    for (int r = 0; r < 2; r++) {
        const int row = row0 + ty * 2 + r;
        float4 o;
        o.x = acc[r][0] + bv4.x;
        o.y = acc[r][1] + bv4.y;
        o.z = acc[r][2] + bv4.z;
        o.w = acc[r][3] + bv4.w;
        *reinterpret_cast<float4*>(&O[row * Cdim + col]) = o;
    }
}

} // namespace

extern "C" void kernel_launch(void* const* d_in, const int* in_sizes, int n_in,
                              void* d_out, int out_size)
{
    const float* feat = (const float*)d_in[0];
    const float* Wv   = (const float*)d_in[9];
    const float* bv   = (const float*)d_in[10];
    float* out        = (float*)d_out;

    dim3 grid(Cdim / TN, Ndim / TM);   // (4, 32) = 128 blocks
    dim3 block(256);
    vgemm_bias_kernel<<<grid, block>>>(feat, Wv, bv, out);
}